// round 4
// baseline (speedup 1.0000x reference)
#include <cuda_runtime.h>
#include <stdint.h>

// ---------------- problem constants (fixed shapes from reference) ----------------
#define RAWN   40962                    // ico-6 nodes
#define FEATN  256
#define NELEM  (RAWN * FEATN)           // 10486272 flat elements
#define NDIV   (NELEM - 1)              // 10486271 linspace divisor (odd, coprime with 256)
#define NNODES 163842                   // ico-7 nodes
#define OUTSZ  ((size_t)NNODES * FEATN) // 41943552 output floats

#define ZBLOCKS 2048                    // blocks dedicated to zeroing y inside K1
#define WARPS_PER_BLOCK 8
#define SCATTER_BLOCKS ((RAWN + WARPS_PER_BLOCK - 1) / WARPS_PER_BLOCK) // 5121
#define NLIST (RAWN * 14)               // max 14 cells (7 cols x 2 feature-rows) per source row

// Scratch (zero-init at module load; K2 restores zeros each run -> deterministic
// graph replays). prio holds (k+1) of the current winning flat index per cell.
__device__ unsigned int g_prio[OUTSZ];  // touched only at ~290K cells per run
__device__ uint4        g_list[NLIST];  // {cell, key(k+1), valbits, 0}; key==0 => empty

// ---------------------------------------------------------------------------------
// Warp-per-source-row dedup + priority scatter, templated on index dtype.
// Processes f in descending order; first surviving write per cell-slot is the
// max-f (= numpy last-write) for that cell within this row. Cross-row ordering
// resolved by atomicMax on flat index k (rows with larger i have larger k).
// ---------------------------------------------------------------------------------
template <typename IT>
__device__ __forceinline__ void scatter_row(
    int i, int lane,
    const float* __restrict__ x,
    const IT*    __restrict__ max_index,
    const IT*    __restrict__ neigh)
{
    const IT* mi = max_index + (size_t)i * FEATN;
    // feature-column index at f=0 for this row: floor(i*256*256 / NDIV)
    const unsigned r0 = (unsigned)(((unsigned long long)i * 65536ull) / (unsigned long long)NDIV);

    unsigned taken = 0;  // bitmask over 14 cell-slots (warp-uniform)

    #pragma unroll
    for (int j = 7; j >= 0; --j) {
        const int f = j * 32 + lane;                          // higher lane = higher f
        const unsigned k = (unsigned)i * 256u + (unsigned)f;  // flat index (< 2^24)
        const int m = (int)mi[f];                             // 0..6
        unsigned r = (unsigned)(((unsigned long long)k * 256ull) / (unsigned long long)NDIV);
        if (r > 255u) r = 255u;                               // reference clamps the final elem
        const int slot = m + 7 * (int)(r - r0);               // 0..13

        const unsigned peers  = __match_any_sync(0xffffffffu, slot);
        const int      leader = 31 - __clz(peers);            // max f in this round
        const bool     win    = (lane == leader) && !((taken >> slot) & 1u);
        const unsigned rslots = __reduce_or_sync(0xffffffffu, 1u << slot);

        if (win) {
            const unsigned c    = (unsigned)neigh[(size_t)i * 7 + m];
            const unsigned cell = c * 256u + r;
            const float    v    = x[(size_t)i * FEATN + f];
            atomicMax(&g_prio[cell], k + 1u);                 // cross-row last-write-wins
            g_list[i * 14 + slot] = make_uint4(cell, k + 1u, __float_as_uint(v), 0u);
        }
        taken |= rslots;
    }
}

// ---------------------------------------------------------------------------------
// K1: fused  (a) zero output   (b) dedup + priority scatter (dtype auto-detected)
// ---------------------------------------------------------------------------------
__global__ void __launch_bounds__(256)
k1_zero_and_scatter(const float* __restrict__ x,
                    const void*  __restrict__ mi_raw,
                    const void*  __restrict__ ng_raw,
                    float* __restrict__ y)
{
    if (blockIdx.x < ZBLOCKS) {
        // ---- zeroing partition: 168 MB of float4 stores, grid-strided ----
        float4* y4 = reinterpret_cast<float4*>(y);
        const size_t n4     = OUTSZ / 4;
        const size_t stride = (size_t)ZBLOCKS * blockDim.x;
        size_t idx = (size_t)blockIdx.x * blockDim.x + threadIdx.x;
        const float4 z = make_float4(0.f, 0.f, 0.f, 0.f);
        for (size_t p = idx; p < n4; p += stride) y4[p] = z;
        return;
    }

    const int warp_global = (((int)blockIdx.x - ZBLOCKS) * (int)blockDim.x + (int)threadIdx.x) >> 5;
    if (warp_global >= RAWN) return;
    const int lane = threadIdx.x & 31;

    // ---- index-dtype detection (JAX x64 disabled => int32 despite jnp.int64) ----
    // If int64: every high word of the first 8 neigh entries is 0 (values < 2^31).
    // If int32: those words are random node ids in [0, 163842) -- effectively never all 0.
    const uint2* probe = reinterpret_cast<const uint2*>(ng_raw);
    unsigned hiw = 0;
    #pragma unroll
    for (int t = 0; t < 8; ++t) hiw |= probe[t].y;

    if (hiw == 0)
        scatter_row<long long>(warp_global, lane, (const float*)mi_raw == nullptr ? nullptr : (const float*)nullptr, // placeholder removed below
                               (const long long*)mi_raw, (const long long*)ng_raw);
    else
        scatter_row<int>(warp_global, lane, (const float*)nullptr,
                         (const int*)mi_raw, (const int*)ng_raw);
}

// NOTE: the two calls above need x; redefine K1 properly (kept single definition):
// (The above block is replaced by the correct implementation below.)

__global__ void __launch_bounds__(256)
k1_main(const float* __restrict__ x,
        const void*  __restrict__ mi_raw,
        const void*  __restrict__ ng_raw,
        float* __restrict__ y)
{
    if (blockIdx.x < ZBLOCKS) {
        float4* y4 = reinterpret_cast<float4*>(y);
        const size_t n4     = OUTSZ / 4;
        const size_t stride = (size_t)ZBLOCKS * blockDim.x;
        size_t idx = (size_t)blockIdx.x * blockDim.x + threadIdx.x;
        const float4 z = make_float4(0.f, 0.f, 0.f, 0.f);
        for (size_t p = idx; p < n4; p += stride) y4[p] = z;
        return;
    }

    const int warp_global = (((int)blockIdx.x - ZBLOCKS) * (int)blockDim.x + (int)threadIdx.x) >> 5;
    if (warp_global >= RAWN) return;
    const int lane = threadIdx.x & 31;

    const uint2* probe = reinterpret_cast<const uint2*>(ng_raw);
    unsigned hiw = 0;
    #pragma unroll
    for (int t = 0; t < 8; ++t) hiw |= probe[t].y;

    if (hiw == 0)
        scatter_row<long long>(warp_global, lane, x,
                               (const long long*)mi_raw, (const long long*)ng_raw);
    else
        scatter_row<int>(warp_global, lane, x,
                         (const int*)mi_raw, (const int*)ng_raw);
}

// ---------------------------------------------------------------------------------
// K2: commit winners to y and restore scratch to zero (self-cleaning for replay)
// ---------------------------------------------------------------------------------
__global__ void __launch_bounds__(256)
k2_commit(float* __restrict__ y)
{
    const unsigned idx = blockIdx.x * blockDim.x + threadIdx.x;
    if (idx >= (unsigned)NLIST) return;
    const uint4 e = g_list[idx];
    if (e.y != 0u) {
        // Exactly one entry per cell holds the max key; only it matches and resets.
        // Losers read either the max key or 0 (post-reset) -- both != their key.
        if (g_prio[e.x] == e.y) {
            y[e.x] = __uint_as_float(e.z);
            g_prio[e.x] = 0u;
        }
        g_list[idx] = make_uint4(0u, 0u, 0u, 0u);
    }
}

// ---------------------------------------------------------------------------------
extern "C" void kernel_launch(void* const* d_in, const int* in_sizes, int n_in,
                              void* d_out, int out_size)
{
    const float* x  = (const float*)d_in[0];
    const void*  mi = (const void*)d_in[1];   // int32 or int64, auto-detected on device
    const void*  ng = (const void*)d_in[2];
    float*       y  = (float*)d_out;

    (void)in_sizes; (void)n_in; (void)out_size;

    k1_main<<<ZBLOCKS + SCATTER_BLOCKS, 256>>>(x, mi, ng, y);
    k2_commit<<<(NLIST + 255) / 256, 256>>>(y);
}

// round 5
// speedup vs baseline: 1.1033x; 1.1033x over previous
#include <cuda_runtime.h>
#include <stdint.h>

// ---------------- problem constants (fixed shapes from reference) ----------------
#define RAWN   40962                    // ico-6 nodes
#define FEATN  256
#define NELEM  (RAWN * FEATN)           // 10486272 flat elements
#define NDIV   (NELEM - 1)              // linspace divisor (coprime with 256)
#define NNODES 163842                   // ico-7 nodes
#define OUTSZ  ((size_t)NNODES * FEATN) // 41943552 output floats

#define ZBLOCKS 2048                    // blocks dedicated to zeroing y inside K1
#define WARPS_PER_BLOCK 8
#define SCATTER_BLOCKS ((RAWN + WARPS_PER_BLOCK - 1) / WARPS_PER_BLOCK) // 5121
#define NSLOTS (RAWN * 14)              // <=14 winner cells (7 cols x 2 rows) per source row
#define K2BLOCKS ((NSLOTS + 255) / 256) // 2241

// Scratch (zero-init at module load; kernels restore zeros each run so CUDA-graph
// replays are deterministic).
// g_packed[cell] = (flat_k+1)<<32 | float_bits : unsigned max == last-write-wins.
__device__ unsigned long long g_packed[OUTSZ];  // touched only at ~290K cells/run
__device__ unsigned int       g_cells[NSLOTS];  // cell+1 per per-row winner slot; 0 = empty

// ---------------------------------------------------------------------------------
// Warp-per-source-row dedup + packed priority scatter, templated on index dtype.
// f processed in descending 32-wide rounds; first surviving write per cell-slot is
// the max-f (numpy last-write) within the row. Cross-row ordering resolved by the
// 64-bit packed atomicMax (fire-and-forget REDG.MAX).
// ---------------------------------------------------------------------------------
template <typename IT>
__device__ __forceinline__ void scatter_row(
    int i, int lane,
    const float* __restrict__ x,
    const IT*    __restrict__ max_index,
    const IT*    __restrict__ neigh)
{
    const IT* mi = max_index + (size_t)i * FEATN;

    // Hoist all 8 per-lane max_index loads: 8 independent loads -> one latency exposure.
    int mval[8];
    #pragma unroll
    for (int j = 0; j < 8; ++j) mval[j] = (int)mi[j * 32 + lane];

    // output feature-column at f=0 for this row: floor(i*65536 / NDIV)
    const unsigned r0 = (unsigned)(((unsigned long long)i * 65536ull) / (unsigned long long)NDIV);

    unsigned taken = 0;  // warp-uniform bitmask over the 14 cell-slots

    #pragma unroll
    for (int j = 7; j >= 0; --j) {
        const int f = j * 32 + lane;                          // higher lane = higher f
        const unsigned k = (unsigned)i * 256u + (unsigned)f;  // flat index (< 2^24)
        const int m = mval[j];                                // 0..6
        unsigned r = (unsigned)(((unsigned long long)k * 256ull) / (unsigned long long)NDIV);
        if (r > 255u) r = 255u;                               // reference clamps the last elem
        const int slot = m + 7 * (int)(r - r0);               // 0..13

        const unsigned peers  = __match_any_sync(0xffffffffu, slot);
        const int      leader = 31 - __clz(peers);            // max f in this round
        const bool     win    = (lane == leader) && !((taken >> slot) & 1u);
        const unsigned rslots = __reduce_or_sync(0xffffffffu, 1u << slot);

        if (win) {
            const unsigned c    = (unsigned)neigh[(size_t)i * 7 + m];
            const unsigned cell = c * 256u + r;
            const unsigned long long pk =
                ((unsigned long long)(k + 1u) << 32) |
                (unsigned long long)__float_as_uint(x[(size_t)i * FEATN + f]);
            atomicMax(&g_packed[cell], pk);     // return unused -> REDG.MAX (no stall)
            g_cells[i * 14 + slot] = cell + 1u; // deterministic slot, plain store
        }
        taken |= rslots;
    }
}

// ---------------------------------------------------------------------------------
// K1: fused  (a) zero output (streaming stores)   (b) dedup + packed scatter
// ---------------------------------------------------------------------------------
__global__ void __launch_bounds__(256)
k1_main(const float* __restrict__ x,
        const void*  __restrict__ mi_raw,
        const void*  __restrict__ ng_raw,
        float* __restrict__ y)
{
    if (blockIdx.x < ZBLOCKS) {
        // zeroing partition: 168 MB of streaming float4 stores (don't pollute L2)
        float4* y4 = reinterpret_cast<float4*>(y);
        const size_t n4     = OUTSZ / 4;
        const size_t stride = (size_t)ZBLOCKS * blockDim.x;
        size_t idx = (size_t)blockIdx.x * blockDim.x + threadIdx.x;
        const float4 z = make_float4(0.f, 0.f, 0.f, 0.f);
        for (size_t p = idx; p < n4; p += stride) __stcs(&y4[p], z);
        return;
    }

    const int warp_global = (((int)blockIdx.x - ZBLOCKS) * (int)blockDim.x + (int)threadIdx.x) >> 5;
    if (warp_global >= RAWN) return;
    const int lane = threadIdx.x & 31;

    // Index-dtype detection (JAX x64 disabled silently yields int32 despite jnp.int64).
    // int64 buffer: high words of first 8 neigh entries are all 0 (values < 2^31).
    // int32 buffer: those words are random node ids -- never all zero in practice.
    const uint2* probe = reinterpret_cast<const uint2*>(ng_raw);
    unsigned hiw = 0;
    #pragma unroll
    for (int t = 0; t < 8; ++t) hiw |= probe[t].y;

    const float* x_ = (const float*)x;
    if (hiw == 0)
        scatter_row<long long>(warp_global, lane, x_,
                               (const long long*)mi_raw, (const long long*)ng_raw);
    else
        scatter_row<int>(warp_global, lane, x_,
                         (const int*)mi_raw, (const int*)ng_raw);
}

// ---------------------------------------------------------------------------------
// K2: commit winners and restore scratch to zero (idempotent via atomicExch).
// Cross-row duplicate entries for one cell: only the first exch sees nonzero.
// ---------------------------------------------------------------------------------
__global__ void __launch_bounds__(256)
k2_commit(float* __restrict__ y)
{
    const unsigned idx = blockIdx.x * blockDim.x + threadIdx.x;
    if (idx >= (unsigned)NSLOTS) return;
    const unsigned e = g_cells[idx];
    if (e != 0u) {
        const unsigned cell = e - 1u;
        const unsigned long long p = atomicExch(&g_packed[cell], 0ull);
        if (p != 0ull)
            y[cell] = __uint_as_float((unsigned)(p & 0xffffffffull));
        g_cells[idx] = 0u;               // restore empty for next replay
    }
}

// ---------------------------------------------------------------------------------
extern "C" void kernel_launch(void* const* d_in, const int* in_sizes, int n_in,
                              void* d_out, int out_size)
{
    const float* x  = (const float*)d_in[0];
    const void*  mi = (const void*)d_in[1];   // int32 or int64, auto-detected on device
    const void*  ng = (const void*)d_in[2];
    float*       y  = (float*)d_out;

    (void)in_sizes; (void)n_in; (void)out_size;

    k1_main<<<ZBLOCKS + SCATTER_BLOCKS, 256>>>(x, mi, ng, y);
    k2_commit<<<K2BLOCKS, 256>>>(y);
}